// round 2
// baseline (speedup 1.0000x reference)
#include <cuda_runtime.h>
#include <cuda_bf16.h>
#include <cstdint>

// out = (((x+2)*3 - 5)/4)^2 = ((3x+1)/4)^2 ; let t = 0.75*x + 0.25, out = t*t
// 8192*8192 fp32 elements = 64M. Pure HBM-streaming kernel.

__global__ __launch_bounds__(256) void ewise_sq_kernel(
    const float4* __restrict__ in, float4* __restrict__ out, int n4)
{
    int i = blockIdx.x * (blockDim.x * 2) + threadIdx.x;
    int stride = blockDim.x;  // second element offset within block's 2x tile

    // Two independent float4 loads per thread -> MLP=2 per thread,
    // ~512B per warp per iteration half.
    if (i < n4) {
        float4 a = in[i];
        float4 r;
        float t0 = fmaf(0.75f, a.x, 0.25f);
        float t1 = fmaf(0.75f, a.y, 0.25f);
        float t2 = fmaf(0.75f, a.z, 0.25f);
        float t3 = fmaf(0.75f, a.w, 0.25f);
        r.x = t0 * t0; r.y = t1 * t1; r.z = t2 * t2; r.w = t3 * t3;
        out[i] = r;
    }
    int j = i + stride;
    if (j < n4) {
        float4 a = in[j];
        float4 r;
        float t0 = fmaf(0.75f, a.x, 0.25f);
        float t1 = fmaf(0.75f, a.y, 0.25f);
        float t2 = fmaf(0.75f, a.z, 0.25f);
        float t3 = fmaf(0.75f, a.w, 0.25f);
        r.x = t0 * t0; r.y = t1 * t1; r.z = t2 * t2; r.w = t3 * t3;
        out[j] = r;
    }
}

extern "C" void kernel_launch(void* const* d_in, const int* in_sizes, int n_in,
                              void* d_out, int out_size)
{
    const float* x = (const float*)d_in[0];
    float* y = (float*)d_out;
    int n = in_sizes[0];          // 67108864
    int n4 = n >> 2;              // 16777216 float4s (n is divisible by 4)

    const int threads = 256;
    const int per_block = threads * 2;                 // 512 float4 per block
    int blocks = (n4 + per_block - 1) / per_block;     // 32768 blocks

    ewise_sq_kernel<<<blocks, threads>>>(
        (const float4*)x, (float4*)y, n4);
}